// round 4
// baseline (speedup 1.0000x reference)
#include <cuda_runtime.h>
#include <math.h>

#define NB 4
#define SL 512
#define VOCAB 32000
#define DD 128
#define MM 8
#define NM 16
#define KK 153
#define LAMBDA 0.0025f
#define SCALE_D 0.08838834764831845f   /* 1/sqrt(128) */
#define SCALE_DH 0.17677669529663687f  /* 1/sqrt(32)  */

// ---------------- scratch ----------------
__device__ float g_x[NB*SL*DD];
__device__ float g_gates[NB*SL*MM];
__device__ float g_conn[SL*MM*MM];
__device__ float g_out[NB*SL*DD];
__device__ float g_q[NB*4*SL*32];
__device__ float g_k[NB*4*SL*32];
__device__ float g_v[NB*4*SL*32];
__device__ float g_ctx[NB*SL*DD];
__device__ float g_d1[NB*SL*DD];

// ---------------- helpers ----------------
__device__ __forceinline__ float wsum(float v) {
#pragma unroll
    for (int o = 16; o; o >>= 1) v += __shfl_xor_sync(0xffffffffu, v, o);
    return v;
}
__device__ __forceinline__ float wmaxf(float v) {
#pragma unroll
    for (int o = 16; o; o >>= 1) v = fmaxf(v, __shfl_xor_sync(0xffffffffu, v, o));
    return v;
}
__device__ __forceinline__ int wsumi(int v) {
#pragma unroll
    for (int o = 16; o; o >>= 1) v += __shfl_xor_sync(0xffffffffu, v, o);
    return v;
}

// ---------------- K0: embedding + pos ----------------
__global__ void embed_kernel(const int* __restrict__ seq,
                             const float* __restrict__ emb,
                             const float* __restrict__ pos) {
    int row = blockIdx.x;            // b*SL + s
    int d = threadIdx.x;
    int s = row & (SL - 1);
    int tok = seq[row];
    g_x[row * DD + d] = emb[tok * DD + d] + pos[s * DD + d];
}

// ---------------- K1: router gates ----------------
__global__ void gates_kernel(const float* __restrict__ Wr1, const float* __restrict__ br1,
                             const float* __restrict__ Wr2, const float* __restrict__ br2) {
    __shared__ float xs[8][DD];
    int warp = threadIdx.x >> 5, lane = threadIdx.x & 31;
    int row = blockIdx.x * 8 + warp;
    const float* xr = g_x + row * DD;
#pragma unroll
    for (int c = 0; c < 4; ++c) xs[warp][lane + 32 * c] = xr[lane + 32 * c];
    __syncwarp();

    float acc[4] = {0.f, 0.f, 0.f, 0.f};
    for (int k = 0; k < DD; ++k) {
        float a = xs[warp][k];
#pragma unroll
        for (int c = 0; c < 4; ++c) acc[c] = fmaf(a, Wr1[k * DD + lane + 32 * c], acc[c]);
    }
    float t1[4];
#pragma unroll
    for (int c = 0; c < 4; ++c) t1[c] = fmaxf(acc[c] + br1[lane + 32 * c], 0.f);

    float y[MM];
#pragma unroll
    for (int m = 0; m < MM; ++m) {
        float p = 0.f;
#pragma unroll
        for (int c = 0; c < 4; ++c) p = fmaf(t1[c], Wr2[(lane + 32 * c) * MM + m], p);
        p = wsum(p);
        y[m] = p + br2[m];
    }
    float mx = y[0];
#pragma unroll
    for (int m = 1; m < MM; ++m) mx = fmaxf(mx, y[m]);
    float ssum = 0.f;
#pragma unroll
    for (int m = 0; m < MM; ++m) { y[m] = expf(y[m] - mx); ssum += y[m]; }
    if (lane == 0) {
        float inv = 1.f / ssum;
#pragma unroll
        for (int m = 0; m < MM; ++m) g_gates[row * MM + m] = y[m] * inv;
    }
}

// ---------------- K2: Hebbian conn prefix ----------------
__global__ void conn_kernel(const float* __restrict__ conn0) {
    extern __shared__ float gs[];   // NB*SL*MM floats
    int tid = threadIdx.x;          // 64 threads
    for (int i = tid; i < NB * SL * MM; i += 64) gs[i] = g_gates[i];
    __syncthreads();
    int i = tid >> 3, j = tid & 7;
    float c = conn0[tid];
    for (int t = 0; t < SL; ++t) {
        g_conn[t * 64 + tid] = c;
        float v = 0.f;
#pragma unroll
        for (int b = 0; b < NB; ++b)
            v += gs[(b * SL + t) * MM + i] * gs[(b * SL + t) * MM + j];
        c += LAMBDA * v;
    }
}

// ---------------- K3: sequential scan, one CTA per batch ----------------
// SMEM float offsets
#define SM_WMSG 0
#define SM_MEM  16384
#define SM_EB1  18432
#define SM_E1G  19456
#define SM_E1B  20480
#define SM_EB2  21504
#define SM_E2G  22528
#define SM_E2B  23552
#define SM_EB3  24576
#define SM_LNG  25600
#define SM_LNB  25728
#define SM_CUR  25856
#define SM_COMB 25984
#define SM_AGG  26112
#define SM_H1   26240
#define SM_H2   27264
#define SM_ST   28288
#define SM_SB   29312
#define SM_YB   30336
#define SM_PART 31360
#define SM_ATT  39552
#define SM_G    39584
#define SM_CONN 39592
#define SM_RS   39656
#define SM_RQ   39688
#define SCAN_SMEM_BYTES (39720 * 4)

// out[m][j] (pre-bias) partials; thread layout kq(4) x m(8) x jv(32)
__device__ __forceinline__ void expert_gemv(const float* __restrict__ W,
                                            const float* inS, int instride,
                                            float* sm, int tid) {
    int kq = tid >> 8, m = (tid >> 5) & 7, jv = tid & 31;
    const float* in = inS + m * instride + kq * 32;
    const float4* W4 = reinterpret_cast<const float4*>(W) + (size_t)((m * 128 + kq * 32) * 32 + jv);
    float4 acc = make_float4(0.f, 0.f, 0.f, 0.f);
#pragma unroll
    for (int k = 0; k < 32; ++k) {
        float a = in[k];
        float4 w = W4[k * 32];
        acc.x = fmaf(a, w.x, acc.x);
        acc.y = fmaf(a, w.y, acc.y);
        acc.z = fmaf(a, w.z, acc.z);
        acc.w = fmaf(a, w.w, acc.w);
    }
    reinterpret_cast<float4*>(sm + SM_PART)[kq * 256 + m * 32 + jv] = acc;
}

// reduce 4 kq partials + bias, LN per module row, relu -> outb
__device__ __forceinline__ void reduce_ln_relu(float* sm, int tid,
                                               int eb_off, int g_off, int b_off,
                                               float* outb) {
    int m = tid >> 7, warp = tid >> 5, lane = tid & 31;
    float v = sm[SM_PART + tid] + sm[SM_PART + 1024 + tid] +
              sm[SM_PART + 2048 + tid] + sm[SM_PART + 3072 + tid] + sm[eb_off + tid];
    float s1 = wsum(v), s2 = wsum(v * v);
    if (lane == 0) { sm[SM_RS + warp] = s1; sm[SM_RQ + warp] = s2; }
    __syncthreads();
    float t1 = sm[SM_RS + (m << 2)] + sm[SM_RS + (m << 2) + 1] +
               sm[SM_RS + (m << 2) + 2] + sm[SM_RS + (m << 2) + 3];
    float t2 = sm[SM_RQ + (m << 2)] + sm[SM_RQ + (m << 2) + 1] +
               sm[SM_RQ + (m << 2) + 2] + sm[SM_RQ + (m << 2) + 3];
    float mean = t1 * (1.f / 128.f);
    float var = t2 * (1.f / 128.f) - mean * mean;
    float inv = rsqrtf(var + 1e-5f);
    float r = (v - mean) * inv * sm[g_off + tid] + sm[b_off + tid];
    outb[tid] = fmaxf(r, 0.f);
}

// softmax over 16 mem slots of dot(vec, mem)*scale -> sm[SM_ATT]
__device__ __forceinline__ void mem_attn(float* sm, int tid, int vec_off) {
    int warp = tid >> 5, lane = tid & 31;
    if (warp < NM) {
        float p = 0.f;
#pragma unroll
        for (int c = 0; c < 4; ++c) {
            int k = lane + 32 * c;
            p = fmaf(sm[vec_off + k], sm[SM_MEM + warp * DD + k], p);
        }
        p = wsum(p);
        if (lane == 0) sm[SM_ATT + warp] = p * SCALE_D;
    }
    __syncthreads();
    if (warp == 0) {
        float vv = (lane < NM) ? sm[SM_ATT + lane] : -1e30f;
        float mx = wmaxf(vv);
        float e = (lane < NM) ? expf(vv - mx) : 0.f;
        float ss = wsum(e);
        if (lane < NM) sm[SM_ATT + lane] = e / ss;
    }
    __syncthreads();
}

__global__ void __launch_bounds__(1024, 1) scan_kernel(
    const float* __restrict__ mem0, const float* __restrict__ Wmsg,
    const float* __restrict__ ln_g, const float* __restrict__ ln_b,
    const float* __restrict__ eW1, const float* __restrict__ eb1,
    const float* __restrict__ e1g, const float* __restrict__ e1b,
    const float* __restrict__ eW2, const float* __restrict__ eb2,
    const float* __restrict__ e2g, const float* __restrict__ e2b,
    const float* __restrict__ eW3, const float* __restrict__ eb3) {
    extern __shared__ float sm[];
    int tid = threadIdx.x, b = blockIdx.x;
    int warp = tid >> 5, lane = tid & 31;

    for (int i = tid; i < 16384; i += 1024) sm[SM_WMSG + i] = Wmsg[i];
    for (int i = tid; i < 2048; i += 1024) sm[SM_MEM + i] = mem0[i];
    sm[SM_EB1 + tid] = eb1[tid];
    sm[SM_E1G + tid] = e1g[tid];
    sm[SM_E1B + tid] = e1b[tid];
    sm[SM_EB2 + tid] = eb2[tid];
    sm[SM_E2G + tid] = e2g[tid];
    sm[SM_E2B + tid] = e2b[tid];
    sm[SM_EB3 + tid] = eb3[tid];
    if (tid < DD) { sm[SM_LNG + tid] = ln_g[tid]; sm[SM_LNB + tid] = ln_b[tid]; }
    __syncthreads();

    for (int t = 0; t < SL; ++t) {
        // step loader
        if (tid < 128) sm[SM_CUR + tid] = g_x[(b * SL + t) * DD + tid];
        else if (tid >= 128 && tid < 136) sm[SM_G + tid - 128] = g_gates[(b * SL + t) * MM + (tid - 128)];
        else if (tid >= 256 && tid < 320) sm[SM_CONN + tid - 256] = g_conn[t * 64 + (tid - 256)];
        __syncthreads();

        // memory attention on cur
        mem_attn(sm, tid, SM_CUR);

        // retrieved + combined (raw)
        if (tid < DD) {
            float rr = 0.f;
#pragma unroll
            for (int n = 0; n < NM; ++n) rr = fmaf(sm[SM_ATT + n], sm[SM_MEM + n * DD + tid], rr);
            sm[SM_COMB + tid] = sm[SM_CUR + tid] + rr;
        }
        __syncthreads();
        // LN(combined)
        float combv = 0.f;
        if (tid < DD) {
            combv = sm[SM_COMB + tid];
            float s1 = wsum(combv), s2 = wsum(combv * combv);
            if (lane == 0) { sm[SM_RS + warp] = s1; sm[SM_RQ + warp] = s2; }
        }
        __syncthreads();
        if (tid < DD) {
            float s1 = sm[SM_RS + 0] + sm[SM_RS + 1] + sm[SM_RS + 2] + sm[SM_RS + 3];
            float s2 = sm[SM_RQ + 0] + sm[SM_RQ + 1] + sm[SM_RQ + 2] + sm[SM_RQ + 3];
            float mean = s1 * (1.f / 128.f);
            float var = s2 * (1.f / 128.f) - mean * mean;
            float inv = rsqrtf(var + 1e-5f);
            sm[SM_COMB + tid] = (combv - mean) * inv * sm[SM_LNG + tid] + sm[SM_LNB + tid];
        }
        __syncthreads();

        // expert layer 1 (broadcast input)
        expert_gemv(eW1, sm + SM_COMB, 0, sm, tid);
        __syncthreads();
        reduce_ln_relu(sm, tid, SM_EB1, SM_E1G, SM_E1B, sm + SM_H1);
        __syncthreads();
        // expert layer 2
        expert_gemv(eW2, sm + SM_H1, 128, sm, tid);
        __syncthreads();
        reduce_ln_relu(sm, tid, SM_EB2, SM_E2G, SM_E2B, sm + SM_H2);
        __syncthreads();
        // expert layer 3 (bias only)
        expert_gemv(eW3, sm + SM_H2, 128, sm, tid);
        __syncthreads();
        {
            float v = sm[SM_PART + tid] + sm[SM_PART + 1024 + tid] +
                      sm[SM_PART + 2048 + tid] + sm[SM_PART + 3072 + tid] + sm[SM_EB3 + tid];
            sm[SM_ST + tid] = v;
            sm[SM_SB + tid] = v;
        }
        __syncthreads();

        // 2 message-passing steps: y[j] = s[j]@Wmsg ; s[i] += relu(sum_j conn[i,j]*g[j]*y[j])
#pragma unroll 1
        for (int mp = 0; mp < 2; ++mp) {
            // y partials: kq(8) x iq(4 -> 2 i's) x dv(32)
            {
                int kq = tid >> 7, iq = (tid >> 5) & 3, dv = tid & 31;
                int i0 = iq * 2, i1 = i0 + 1;
                const float4* Wm4 = reinterpret_cast<const float4*>(sm + SM_WMSG);
                float4 a0 = make_float4(0.f, 0.f, 0.f, 0.f);
                float4 a1 = make_float4(0.f, 0.f, 0.f, 0.f);
#pragma unroll
                for (int k = 0; k < 16; ++k) {
                    int kg = kq * 16 + k;
                    float4 w = Wm4[kg * 32 + dv];
                    float u0 = sm[SM_SB + i0 * 128 + kg];
                    float u1 = sm[SM_SB + i1 * 128 + kg];
                    a0.x = fmaf(u0, w.x, a0.x); a0.y = fmaf(u0, w.y, a0.y);
                    a0.z = fmaf(u0, w.z, a0.z); a0.w = fmaf(u0, w.w, a0.w);
                    a1.x = fmaf(u1, w.x, a1.x); a1.y = fmaf(u1, w.y, a1.y);
                    a1.z = fmaf(u1, w.z, a1.z); a1.w = fmaf(u1, w.w, a1.w);
                }
                float4* p4 = reinterpret_cast<float4*>(sm + SM_PART);
                p4[kq * 256 + i0 * 32 + dv] = a0;
                p4[kq * 256 + i1 * 32 + dv] = a1;
            }
            __syncthreads();
            {
                float y = 0.f;
#pragma unroll
                for (int kq = 0; kq < 8; ++kq) y += sm[SM_PART + kq * 1024 + tid];
                sm[SM_YB + tid] = y;
            }
            __syncthreads();
            {
                int i = tid >> 7, d = tid & 127;
                float mpv = 0.f;
#pragma unroll
                for (int j = 0; j < MM; ++j)
                    mpv = fmaf(sm[SM_CONN + i * 8 + j] * sm[SM_G + j], sm[SM_YB + j * 128 + d], mpv);
                sm[SM_SB + tid] += fmaxf(mpv, 0.f);
            }
            __syncthreads();
        }

        // agg = sum_m g[m]*states[m] + mean_m s[m]
        if (tid < DD) {
            float a = 0.f, ms = 0.f;
#pragma unroll
            for (int m = 0; m < MM; ++m) {
                a = fmaf(sm[SM_G + m], sm[SM_ST + m * 128 + tid], a);
                ms += sm[SM_SB + m * 128 + tid];
            }
            sm[SM_AGG + tid] = a + 0.125f * ms;
        }
        __syncthreads();

        // write-attention on agg, mem update, output
        mem_attn(sm, tid, SM_AGG);
        for (int e = tid; e < 2048; e += 1024) {
            int n = e >> 7, d = e & 127;
            sm[SM_MEM + e] += sm[SM_ATT + n] * sm[SM_AGG + d];
        }
        if (tid < DD) g_out[(b * SL + t) * DD + tid] = sm[SM_AGG + tid];
        __syncthreads();
    }
}

// ---------------- K4: QKV projections ----------------
__global__ void qkv_kernel(const float* __restrict__ Wq, const float* __restrict__ Wk,
                           const float* __restrict__ Wv) {
    __shared__ float xs[32 * 128];
    int tid = threadIdx.x;
    int rowbase = blockIdx.x * 32;
    for (int idx = tid; idx < 4096; idx += 256) xs[idx] = g_out[rowbase * 128 + idx];
    __syncthreads();
    int rh = tid >> 7, jj = tid & 127;
    const float* Ws[3] = {Wq, Wk, Wv};
    float* Os[3] = {g_q, g_k, g_v};
#pragma unroll 1
    for (int w = 0; w < 3; ++w) {
        float acc[16];
#pragma unroll
        for (int r = 0; r < 16; ++r) acc[r] = 0.f;
        const float* W = Ws[w];
        for (int k = 0; k < 128; ++k) {
            float wv = W[k * 128 + jj];
#pragma unroll
            for (int r = 0; r < 16; ++r) acc[r] = fmaf(xs[(rh * 16 + r) * 128 + k], wv, acc[r]);
        }
        int h = jj >> 5, dh = jj & 31;
#pragma unroll
        for (int r = 0; r < 16; ++r) {
            int row = rowbase + rh * 16 + r;
            int bb = row >> 9, s = row & 511;
            Os[w][((bb * 4 + h) * SL + s) * 32 + dh] = acc[r];
        }
    }
}

// ---------------- K5: sparse attention ----------------
__global__ void __launch_bounds__(256) attn_kernel() {
    extern __shared__ float ash[];
    float* kt = ash;              // 16384
    float* vt = ash + 16384;      // 16384
    float* cp = ash + 32768;      // 8192
    int tid = threadIdx.x, warp = tid >> 5, lane = tid & 31;
    int bh = blockIdx.x;
    const float* kb = g_k + bh * SL * 32;
    const float* vb = g_v + bh * SL * 32;
    for (int idx = tid; idx < SL * 32; idx += 256) {
        int n = idx >> 5, dh = idx & 31, sw = (dh + n) & 31;
        kt[n * 32 + sw] = kb[idx];
        vt[n * 32 + sw] = vb[idx];
    }
    __syncthreads();

    int qrow = blockIdx.y * 8 + warp;
    float qv = g_q[bh * SL * 32 + qrow * 32 + lane];
    float sc[16];
#pragma unroll
    for (int c = 0; c < 16; ++c) sc[c] = 0.f;
    for (int dh = 0; dh < 32; ++dh) {
        float qd = __shfl_sync(0xffffffffu, qv, dh);
#pragma unroll
        for (int c = 0; c < 16; ++c) {
            int n = c * 32 + lane;
            sc[c] = fmaf(qd, kt[n * 32 + ((dh + n) & 31)], sc[c]);
        }
    }
#pragma unroll
    for (int c = 0; c < 16; ++c) sc[c] *= SCALE_DH;

    // exact top-KK threshold by binary search on monotone uint encoding
    unsigned eu[16];
#pragma unroll
    for (int c = 0; c < 16; ++c) {
        unsigned u = __float_as_uint(sc[c]);
        eu[c] = (u & 0x80000000u) ? ~u : (u | 0x80000000u);
    }
    unsigned thr = 0;
    for (int bit = 31; bit >= 0; --bit) {
        unsigned cand = thr | (1u << bit);
        int cnt = 0;
#pragma unroll
        for (int c = 0; c < 16; ++c) cnt += (eu[c] >= cand) ? 1 : 0;
        cnt = wsumi(cnt);
        if (cnt >= KK) thr = cand;
    }

    float mloc = -1e30f;
#pragma unroll
    for (int c = 0; c < 16; ++c) mloc = fmaxf(mloc, sc[c]);
    float mx = wmaxf(mloc);
    float ssum = 0.f;
#pragma unroll
    for (int c = 0; c < 16; ++c) ssum += (eu[c] >= thr) ? expf(sc[c] - mx) : 0.f;
    ssum = wsum(ssum);
    float inv = 1.f / ssum;

    float cx[32];
#pragma unroll
    for (int dh = 0; dh < 32; ++dh) cx[dh] = 0.f;
#pragma unroll 1
    for (int c = 0; c < 16; ++c) {
        float a = (eu[c] >= thr) ? expf(sc[c] - mx) * inv : 0.f;
        int n = c * 32 + lane;
#pragma unroll
        for (int dh = 0; dh < 32; ++dh)
            cx[dh] = fmaf(a, vt[n * 32 + ((dh + n) & 31)], cx[dh]);
    }

    float* cw = cp + warp * 1024;
#pragma unroll
    for (int dh = 0; dh < 32; ++dh) cw[lane * 32 + ((dh + lane) & 31)] = cx[dh];
    __syncwarp();
    float tot = 0.f;
#pragma unroll
    for (int src = 0; src < 32; ++src) tot += cw[src * 32 + ((lane + src) & 31)];
    int bb = bh >> 2, h = bh & 3;
    g_ctx[(bb * SL + qrow) * DD + h * 32 + lane] = tot;
}

// ---------------- K6: small 128x128 GEMMs ----------------
__global__ void gemm128_kernel(const float* __restrict__ W, const float* __restrict__ bias,
                               int mode) {
    __shared__ float xs[32 * 128];
    const float* in = mode ? g_out : g_ctx;
    float* out = mode ? g_d1 : g_out;
    int tid = threadIdx.x;
    int rowbase = blockIdx.x * 32;
    for (int idx = tid; idx < 4096; idx += 256) xs[idx] = in[rowbase * 128 + idx];
    __syncthreads();
    int rh = tid >> 7, jj = tid & 127;
    float acc[16];
#pragma unroll
    for (int r = 0; r < 16; ++r) acc[r] = 0.f;
    for (int k = 0; k < 128; ++k) {
        float wv = W[k * 128 + jj];
#pragma unroll
        for (int r = 0; r < 16; ++r) acc[r] = fmaf(xs[(rh * 16 + r) * 128 + k], wv, acc[r]);
    }
    float bb = mode ? bias[jj] : 0.f;
#pragma unroll
    for (int r = 0; r < 16; ++r) {
        float v = acc[r] + bb;
        if (mode) v = fmaxf(v, 0.f);
        out[(rowbase + rh * 16 + r) * 128 + jj] = v;
    }
}

// ---------------- K7: decoder [2048,128]@[128,32000] ----------------
__global__ void __launch_bounds__(256) decoder_kernel(const float* __restrict__ Wd2,
                                                      const float* __restrict__ bd2,
                                                      float* __restrict__ out) {
    extern __shared__ float At[];   // 128*132 transposed A tile
    int tid = threadIdx.x;
    int rowbase = blockIdx.x * 128;
    for (int idx = tid; idx < 16384; idx += 256) {
        int r = idx >> 7, k = idx & 127;
        At[k * 132 + r] = g_d1[(rowbase + r) * 128 + k];
    }
    __syncthreads();
    int j = blockIdx.y * 64 + (tid & 63);
    int rq = tid >> 6;
    float acc[32];
#pragma unroll
    for (int r = 0; r < 32; ++r) acc[r] = 0.f;
    const float* Bp = Wd2 + j;
    for (int k = 0; k < 128; ++k) {
        float w = Bp[(size_t)k * VOCAB];
        const float4* a4 = reinterpret_cast<const float4*>(At + k * 132) + rq * 8;
#pragma unroll
        for (int rr = 0; rr < 8; ++rr) {
            float4 a = a4[rr];
            acc[rr * 4 + 0] = fmaf(a.x, w, acc[rr * 4 + 0]);
            acc[rr * 4 + 1] = fmaf(a.y, w, acc[rr * 4 + 1]);
            acc[rr * 4 + 2] = fmaf(a.z, w, acc[rr * 4 + 2]);
            acc[rr * 4 + 3] = fmaf(a.w, w, acc[rr * 4 + 3]);
        }
    }
    float bb = bd2[j];
#pragma unroll
    for (int rr = 0; rr < 8; ++rr)
#pragma unroll
        for (int c = 0; c < 4; ++c) {
            int row = rowbase + rq * 32 + rr * 4 + c;
            out[(size_t)row * VOCAB + j] = acc[rr * 4 + c] + bb;
        }
}

// ---------------- launch ----------------
extern "C" void kernel_launch(void* const* d_in, const int* in_sizes, int n_in,
                              void* d_out, int out_size) {
    int off = (n_in > 30) ? 1 : 0;  // skip task_id if present
    const int*   seq  = (const int*)d_in[0];
    const float* emb  = (const float*)d_in[1 + off];
    const float* pos  = (const float*)d_in[2 + off];
    const float* Wr1  = (const float*)d_in[3 + off];
    const float* br1  = (const float*)d_in[4 + off];
    const float* Wr2  = (const float*)d_in[5 + off];
    const float* br2  = (const float*)d_in[6 + off];
    const float* ln_g = (const float*)d_in[7 + off];
    const float* ln_b = (const float*)d_in[8 + off];
    const float* eW1  = (const float*)d_in[9 + off];
    const float* eb1  = (const float*)d_in[10 + off];
    const float* e1g  = (const float*)d_in[11 + off];
    const float* e1b  = (const float*)d_in[12 + off];
    const float* eW2  = (const float*)d_in[13 + off];
    const float* eb2  = (const float*)d_in[14 + off];
    const float* e2g  = (const float*)d_in[15 + off];
    const float* e2b  = (const float*)d_in[16 + off];
    const float* eW3  = (const float*)d_in[17 + off];
    const float* eb3  = (const float*)d_in[18 + off];
    const float* mem0 = (const float*)d_in[19 + off];
    const float* Wmsg = (const float*)d_in[20 + off];
    const float* conn0= (const float*)d_in[21 + off];
    const float* Wq   = (const float*)d_in[22 + off];
    const float* Wk   = (const float*)d_in[23 + off];
    const float* Wv   = (const float*)d_in[24 + off];
    const float* Wo   = (const float*)d_in[25 + off];
    const float* Wd1  = (const float*)d_in[26 + off];
    const float* bd1  = (const float*)d_in[27 + off];
    const float* Wd2  = (const float*)d_in[28 + off];
    const float* bd2  = (const float*)d_in[29 + off];

    cudaFuncSetAttribute(conn_kernel, cudaFuncAttributeMaxDynamicSharedMemorySize, NB * SL * MM * 4);
    cudaFuncSetAttribute(scan_kernel, cudaFuncAttributeMaxDynamicSharedMemorySize, SCAN_SMEM_BYTES);
    cudaFuncSetAttribute(attn_kernel, cudaFuncAttributeMaxDynamicSharedMemorySize, 40960 * 4);
    cudaFuncSetAttribute(decoder_kernel, cudaFuncAttributeMaxDynamicSharedMemorySize, 128 * 132 * 4);

    embed_kernel<<<NB * SL, DD>>>(seq, emb, pos);
    gates_kernel<<<NB * SL / 8, 256>>>(Wr1, br1, Wr2, br2);
    conn_kernel<<<1, 64, NB * SL * MM * 4>>>(conn0);
    scan_kernel<<<NB, 1024, SCAN_SMEM_BYTES>>>(mem0, Wmsg, ln_g, ln_b,
                                               eW1, eb1, e1g, e1b,
                                               eW2, eb2, e2g, e2b, eW3, eb3);
    qkv_kernel<<<NB * SL / 32, 256>>>(Wq, Wk, Wv);
    attn_kernel<<<dim3(NB * 4, SL / 8), 256, 40960 * 4>>>();
    gemm128_kernel<<<NB * SL / 32, 256>>>(Wo, bd1, 0);   // ctx @ Wo -> g_out
    gemm128_kernel<<<NB * SL / 32, 256>>>(Wd1, bd1, 1);  // relu(g_out @ Wd1 + bd1) -> g_d1
    decoder_kernel<<<dim3(NB * SL / 128, VOCAB / 64), 256, 128 * 132 * 4>>>(Wd2, bd2, (float*)d_out);
}

// round 5
// speedup vs baseline: 1.6123x; 1.6123x over previous
#include <cuda_runtime.h>
#include <cooperative_groups.h>
#include <math.h>

namespace cg = cooperative_groups;

#define NB 4
#define SL 512
#define VOCAB 32000
#define DD 128
#define MM 8
#define NM 16
#define KK 153
#define LAMBDA 0.0025f
#define SCALE_D 0.08838834764831845f   /* 1/sqrt(128) */
#define SCALE_DH 0.17677669529663687f  /* 1/sqrt(32)  */

// ---------------- scratch ----------------
__device__ float g_x[NB*SL*DD];
__device__ float g_gates[NB*SL*MM];
__device__ float g_conn[SL*MM*MM];
__device__ float g_out[NB*SL*DD];
__device__ float g_q[NB*4*SL*32];
__device__ float g_k[NB*4*SL*32];
__device__ float g_v[NB*4*SL*32];
__device__ float g_ctx[NB*SL*DD];
__device__ float g_d1[NB*SL*DD];

// ---------------- helpers ----------------
__device__ __forceinline__ float wsum(float v) {
#pragma unroll
    for (int o = 16; o; o >>= 1) v += __shfl_xor_sync(0xffffffffu, v, o);
    return v;
}
__device__ __forceinline__ float wmaxf(float v) {
#pragma unroll
    for (int o = 16; o; o >>= 1) v = fmaxf(v, __shfl_xor_sync(0xffffffffu, v, o));
    return v;
}
__device__ __forceinline__ int wsumi(int v) {
#pragma unroll
    for (int o = 16; o; o >>= 1) v += __shfl_xor_sync(0xffffffffu, v, o);
    return v;
}

// ---------------- K0: embedding + pos ----------------
__global__ void embed_kernel(const int* __restrict__ seq,
                             const float* __restrict__ emb,
                             const float* __restrict__ pos) {
    int row = blockIdx.x;            // b*SL + s
    int d = threadIdx.x;
    int s = row & (SL - 1);
    int tok = seq[row];
    g_x[row * DD + d] = emb[tok * DD + d] + pos[s * DD + d];
}

// ---------------- K1: router gates ----------------
__global__ void gates_kernel(const float* __restrict__ Wr1, const float* __restrict__ br1,
                             const float* __restrict__ Wr2, const float* __restrict__ br2) {
    __shared__ float xs[8][DD];
    int warp = threadIdx.x >> 5, lane = threadIdx.x & 31;
    int row = blockIdx.x * 8 + warp;
    const float* xr = g_x + row * DD;
#pragma unroll
    for (int c = 0; c < 4; ++c) xs[warp][lane + 32 * c] = xr[lane + 32 * c];
    __syncwarp();

    float acc[4] = {0.f, 0.f, 0.f, 0.f};
    for (int k = 0; k < DD; ++k) {
        float a = xs[warp][k];
#pragma unroll
        for (int c = 0; c < 4; ++c) acc[c] = fmaf(a, Wr1[k * DD + lane + 32 * c], acc[c]);
    }
    float t1[4];
#pragma unroll
    for (int c = 0; c < 4; ++c) t1[c] = fmaxf(acc[c] + br1[lane + 32 * c], 0.f);

    float y[MM];
#pragma unroll
    for (int m = 0; m < MM; ++m) {
        float p = 0.f;
#pragma unroll
        for (int c = 0; c < 4; ++c) p = fmaf(t1[c], Wr2[(lane + 32 * c) * MM + m], p);
        p = wsum(p);
        y[m] = p + br2[m];
    }
    float mx = y[0];
#pragma unroll
    for (int m = 1; m < MM; ++m) mx = fmaxf(mx, y[m]);
    float ssum = 0.f;
#pragma unroll
    for (int m = 0; m < MM; ++m) { y[m] = expf(y[m] - mx); ssum += y[m]; }
    if (lane == 0) {
        float inv = 1.f / ssum;
#pragma unroll
        for (int m = 0; m < MM; ++m) g_gates[row * MM + m] = y[m] * inv;
    }
}

// ---------------- K2: Hebbian conn prefix ----------------
__global__ void conn_kernel(const float* __restrict__ conn0) {
    extern __shared__ float gs[];   // NB*SL*MM floats
    int tid = threadIdx.x;          // 64 threads
    for (int i = tid; i < NB * SL * MM; i += 64) gs[i] = g_gates[i];
    __syncthreads();
    int i = tid >> 3, j = tid & 7;
    float c = conn0[tid];
    for (int t = 0; t < SL; ++t) {
        g_conn[t * 64 + tid] = c;
        float v = 0.f;
#pragma unroll
        for (int b = 0; b < NB; ++b)
            v += gs[(b * SL + t) * MM + i] * gs[(b * SL + t) * MM + j];
        c += LAMBDA * v;
    }
}

// ---------------- K3: scan — 8-CTA cluster per batch, module-split ----------------
// SMEM float offsets
#define XW1   0        // 16384 (own module eW1)
#define XW2   16384
#define XW3   32768
#define XMEM  49152    // 2048
#define XB1   51200
#define XE1G  51328
#define XE1B  51456
#define XB2   51584
#define XE2G  51712
#define XE2B  51840
#define XB3   51968
#define XLNG  52096
#define XLNB  52224
#define XCUR  52352
#define XCOMB 52480
#define XH1   52608
#define XH2   52736
#define XMSG  52864
#define XAGG  52992
#define XSOWN 53120
#define XEX0  53248
#define XEX1  53376
#define XEX2  53504
#define XST   53632    // 1024 all-module states
#define XSA   54656    // 1024 all-module s
#define XPART 55680    // 128
#define XATT  55808    // 16
#define XG    55824    // 8
#define XCR   55832    // 8
#define XCG   55840    // 8
#define XRS   55848    // 8
#define XRQ   55856    // 8
#define XTOT  55872
#define SCAN_SMEM_BYTES (XTOT * 4)

// 16-slot memory attention, replicated (256 threads, 8 warps x 2 slots)
__device__ __forceinline__ void mem_attn8(float* sm, int tid, int vecoff) {
    int warp = tid >> 5, lane = tid & 31;
    float p0 = 0.f, p1 = 0.f;
#pragma unroll
    for (int c = 0; c < 4; ++c) {
        int k = lane + 32 * c;
        float xv = sm[vecoff + k];
        p0 = fmaf(xv, sm[XMEM + (2 * warp) * DD + k], p0);
        p1 = fmaf(xv, sm[XMEM + (2 * warp + 1) * DD + k], p1);
    }
    p0 = wsum(p0); p1 = wsum(p1);
    if (lane == 0) {
        sm[XATT + 2 * warp] = p0 * SCALE_D;
        sm[XATT + 2 * warp + 1] = p1 * SCALE_D;
    }
    __syncthreads();
    if (warp == 0) {
        float vv = (lane < NM) ? sm[XATT + lane] : -1e30f;
        float mx = wmaxf(vv);
        float e = (lane < NM) ? expf(vv - mx) : 0.f;
        float ss = wsum(e);
        if (lane < NM) sm[XATT + lane] = e / ss;
    }
    __syncthreads();
}

// 64-k half matvec: thread j=tid&127 handles output j, kh=tid>>7 handles k-half
__device__ __forceinline__ float mv_half(const float* __restrict__ W, const float* __restrict__ ip,
                                         int j, int kh) {
    const float* Wp = W + kh * 64 * 128 + j;
    const float* xp = ip + kh * 64;
    float acc = 0.f;
#pragma unroll
    for (int k = 0; k < 64; ++k) acc = fmaf(xp[k], Wp[k * 128], acc);
    return acc;
}

// LN (over 128 outputs) of v (valid tid<128), optional relu, write dst
__device__ __forceinline__ void ln_write(float* sm, int tid, float v,
                                         int goff, int boff, int dstoff, bool do_relu) {
    int warp = tid >> 5, lane = tid & 31;
    if (tid < 128) {
        float s1 = wsum(v), s2 = wsum(v * v);
        if (lane == 0) { sm[XRS + warp] = s1; sm[XRQ + warp] = s2; }
    }
    __syncthreads();
    if (tid < 128) {
        float t1 = sm[XRS + 0] + sm[XRS + 1] + sm[XRS + 2] + sm[XRS + 3];
        float t2 = sm[XRQ + 0] + sm[XRQ + 1] + sm[XRQ + 2] + sm[XRQ + 3];
        float mean = t1 * (1.f / 128.f);
        float var = t2 * (1.f / 128.f) - mean * mean;
        float inv = rsqrtf(var + 1e-5f);
        float r = (v - mean) * inv * sm[goff + tid] + sm[boff + tid];
        sm[dstoff + tid] = do_relu ? fmaxf(r, 0.f) : r;
    }
    __syncthreads();
}

// DSMEM exchange: all CTAs wrote sm[exoff..exoff+128); gather all 8 ranks into dstoff
__device__ __forceinline__ void exch(cg::cluster_group& cl, float* sm, int exoff, int dstoff, int tid) {
    cl.sync();
    int r = tid >> 5, l = tid & 31;
    const float4* rs = (const float4*)cl.map_shared_rank(sm + exoff, r);
    reinterpret_cast<float4*>(sm + dstoff)[r * 32 + l] = rs[l];
    __syncthreads();
}

__global__ void __launch_bounds__(256, 1) __cluster_dims__(MM, 1, 1) scan_kernel(
    const float* __restrict__ mem0, const float* __restrict__ Wmsg,
    const float* __restrict__ ln_g, const float* __restrict__ ln_b,
    const float* __restrict__ eW1, const float* __restrict__ eb1,
    const float* __restrict__ e1g, const float* __restrict__ e1b,
    const float* __restrict__ eW2, const float* __restrict__ eb2,
    const float* __restrict__ e2g, const float* __restrict__ e2b,
    const float* __restrict__ eW3, const float* __restrict__ eb3) {
    extern __shared__ float sm[];
    cg::cluster_group cluster = cg::this_cluster();
    int tid = threadIdx.x;
    int rank = (int)cluster.block_rank();        // module index
    int b = blockIdx.x >> 3;                     // batch index
    int j = tid & 127, kh = tid >> 7;

    // one-time loads: own module weights (192 KB), mem, biases/LN params
    {
        const float* w1 = eW1 + (size_t)rank * 16384;
        const float* w2 = eW2 + (size_t)rank * 16384;
        const float* w3 = eW3 + (size_t)rank * 16384;
        for (int i = tid; i < 16384; i += 256) {
            sm[XW1 + i] = w1[i];
            sm[XW2 + i] = w2[i];
            sm[XW3 + i] = w3[i];
        }
        for (int i = tid; i < 2048; i += 256) sm[XMEM + i] = mem0[i];
        if (tid < 128) {
            sm[XB1 + tid]  = eb1[rank * 128 + tid];
            sm[XE1G + tid] = e1g[rank * 128 + tid];
            sm[XE1B + tid] = e1b[rank * 128 + tid];
            sm[XB2 + tid]  = eb2[rank * 128 + tid];
            sm[XE2G + tid] = e2g[rank * 128 + tid];
            sm[XE2B + tid] = e2b[rank * 128 + tid];
            sm[XB3 + tid]  = eb3[rank * 128 + tid];
            sm[XLNG + tid] = ln_g[tid];
            sm[XLNB + tid] = ln_b[tid];
        }
    }
    __syncthreads();

    for (int t = 0; t < SL; ++t) {
        // step loader
        if (tid < 128) sm[XCUR + tid] = g_x[(b * SL + t) * DD + tid];
        else if (tid < 136) sm[XG + tid - 128] = g_gates[(b * SL + t) * MM + (tid - 128)];
        else if (tid < 144) sm[XCR + tid - 136] = g_conn[t * 64 + rank * 8 + (tid - 136)];
        __syncthreads();
        if (tid < 8) sm[XCG + tid] = sm[XCR + tid] * sm[XG + tid];

        // read-attention over memory (replicated)
        mem_attn8(sm, tid, XCUR);

        // retrieved + combined, LN
        float combv = 0.f;
        if (tid < 128) {
            float rr = 0.f;
#pragma unroll
            for (int n = 0; n < NM; ++n) rr = fmaf(sm[XATT + n], sm[XMEM + n * DD + tid], rr);
            combv = sm[XCUR + tid] + rr;
        }
        ln_write(sm, tid, combv, XLNG, XLNB, XCOMB, false);

        // expert layer 1 (own module, SMEM weights)
        {
            float acc = mv_half(sm + XW1, sm + XCOMB, j, kh);
            if (kh) sm[XPART + j] = acc;
            __syncthreads();
            float v = (tid < 128) ? (acc + sm[XPART + tid] + sm[XB1 + tid]) : 0.f;
            ln_write(sm, tid, v, XE1G, XE1B, XH1, true);
        }
        // expert layer 2
        {
            float acc = mv_half(sm + XW2, sm + XH1, j, kh);
            if (kh) sm[XPART + j] = acc;
            __syncthreads();
            float v = (tid < 128) ? (acc + sm[XPART + tid] + sm[XB2 + tid]) : 0.f;
            ln_write(sm, tid, v, XE2G, XE2B, XH2, true);
        }
        // expert layer 3 -> own state
        {
            float acc = mv_half(sm + XW3, sm + XH2, j, kh);
            if (kh) sm[XPART + j] = acc;
            __syncthreads();
            if (tid < 128) {
                float v = acc + sm[XPART + tid] + sm[XB3 + tid];
                sm[XSOWN + tid] = v;
                sm[XEX0 + tid] = v;
            }
        }
        // exchange states -> XST (includes cluster.sync)
        exch(cluster, sm, XEX0, XST, tid);

        // MP step 1: msg_i from XST, y = relu(msg @ Wmsg), s_own += y
        if (tid < 128) {
            float mv = 0.f;
#pragma unroll
            for (int jm = 0; jm < MM; ++jm)
                mv = fmaf(sm[XCG + jm], sm[XST + jm * 128 + tid], mv);
            sm[XMSG + tid] = mv;
        }
        __syncthreads();
        {
            const float* Wp = Wmsg + kh * 64 * 128 + j;
            const float* xp = sm + XMSG + kh * 64;
            float acc = 0.f;
#pragma unroll 16
            for (int k = 0; k < 64; ++k) acc = fmaf(xp[k], Wp[k * 128], acc);
            if (kh) sm[XPART + j] = acc;
            __syncthreads();
            if (tid < 128) {
                float y = acc + sm[XPART + tid];
                float ns = sm[XSOWN + tid] + fmaxf(y, 0.f);
                sm[XSOWN + tid] = ns;
                sm[XEX1 + tid] = ns;
            }
        }
        exch(cluster, sm, XEX1, XSA, tid);

        // MP step 2: msg_i from XSA
        if (tid < 128) {
            float mv = 0.f;
#pragma unroll
            for (int jm = 0; jm < MM; ++jm)
                mv = fmaf(sm[XCG + jm], sm[XSA + jm * 128 + tid], mv);
            sm[XMSG + tid] = mv;
        }
        __syncthreads();
        {
            const float* Wp = Wmsg + kh * 64 * 128 + j;
            const float* xp = sm + XMSG + kh * 64;
            float acc = 0.f;
#pragma unroll 16
            for (int k = 0; k < 64; ++k) acc = fmaf(xp[k], Wp[k * 128], acc);
            if (kh) sm[XPART + j] = acc;
            __syncthreads();
            if (tid < 128) {
                float y = acc + sm[XPART + tid];
                float ns = sm[XSOWN + tid] + fmaxf(y, 0.f);
                sm[XEX2 + tid] = ns;
            }
        }
        exch(cluster, sm, XEX2, XSA, tid);

        // agg = sum_m g_m * states_m + mean_m s_m (replicated)
        if (tid < 128) {
            float a = 0.f, ms = 0.f;
#pragma unroll
            for (int m = 0; m < MM; ++m) {
                a = fmaf(sm[XG + m], sm[XST + m * 128 + tid], a);
                ms += sm[XSA + m * 128 + tid];
            }
            sm[XAGG + tid] = a + 0.125f * ms;
        }
        __syncthreads();

        // write-attention + memory update (replicated, deterministic)
        mem_attn8(sm, tid, XAGG);
        for (int e = tid; e < 2048; e += 256) {
            int n = e >> 7, d = e & 127;
            sm[XMEM + e] += sm[XATT + n] * sm[XAGG + d];
        }
        if (rank == 0 && tid < 128) g_out[(b * SL + t) * DD + tid] = sm[XAGG + tid];
        __syncthreads();
    }
}

// ---------------- K4: QKV projections ----------------
__global__ void qkv_kernel(const float* __restrict__ Wq, const float* __restrict__ Wk,
                           const float* __restrict__ Wv) {
    __shared__ float xs[32 * 128];
    int tid = threadIdx.x;
    int rowbase = blockIdx.x * 32;
    for (int idx = tid; idx < 4096; idx += 256) xs[idx] = g_out[rowbase * 128 + idx];
    __syncthreads();
    int rh = tid >> 7, jj = tid & 127;
    const float* Ws[3] = {Wq, Wk, Wv};
    float* Os[3] = {g_q, g_k, g_v};
#pragma unroll 1
    for (int w = 0; w < 3; ++w) {
        float acc[16];
#pragma unroll
        for (int r = 0; r < 16; ++r) acc[r] = 0.f;
        const float* W = Ws[w];
        for (int k = 0; k < 128; ++k) {
            float wv = W[k * 128 + jj];
#pragma unroll
            for (int r = 0; r < 16; ++r) acc[r] = fmaf(xs[(rh * 16 + r) * 128 + k], wv, acc[r]);
        }
        int h = jj >> 5, dh = jj & 31;
#pragma unroll
        for (int r = 0; r < 16; ++r) {
            int row = rowbase + rh * 16 + r;
            int bb = row >> 9, s = row & 511;
            Os[w][((bb * 4 + h) * SL + s) * 32 + dh] = acc[r];
        }
    }
}

// ---------------- K5: sparse attention ----------------
__global__ void __launch_bounds__(256) attn_kernel() {
    extern __shared__ float ash[];
    float* kt = ash;              // 16384
    float* vt = ash + 16384;      // 16384
    float* cp = ash + 32768;      // 8192
    int tid = threadIdx.x, warp = tid >> 5, lane = tid & 31;
    int bh = blockIdx.x;
    const float* kb = g_k + bh * SL * 32;
    const float* vb = g_v + bh * SL * 32;
    for (int idx = tid; idx < SL * 32; idx += 256) {
        int n = idx >> 5, dh = idx & 31, sw = (dh + n) & 31;
        kt[n * 32 + sw] = kb[idx];
        vt[n * 32 + sw] = vb[idx];
    }
    __syncthreads();

    int qrow = blockIdx.y * 8 + warp;
    float qv = g_q[bh * SL * 32 + qrow * 32 + lane];
    float sc[16];
#pragma unroll
    for (int c = 0; c < 16; ++c) sc[c] = 0.f;
    for (int dh = 0; dh < 32; ++dh) {
        float qd = __shfl_sync(0xffffffffu, qv, dh);
#pragma unroll
        for (int c = 0; c < 16; ++c) {
            int n = c * 32 + lane;
            sc[c] = fmaf(qd, kt[n * 32 + ((dh + n) & 31)], sc[c]);
        }
    }
#pragma unroll
    for (int c = 0; c < 16; ++c) sc[c] *= SCALE_DH;

    // exact top-KK threshold by binary search on monotone uint encoding
    unsigned eu[16];
#pragma unroll
    for (int c = 0; c < 16; ++c) {
        unsigned u = __float_as_uint(sc[c]);
        eu[c] = (u & 0x80000000u) ? ~u : (u | 0x80000000u);
    }
    unsigned thr = 0;
    for (int bit = 31; bit >= 0; --bit) {
        unsigned cand = thr | (1u << bit);
        int cnt = 0;
#pragma unroll
        for (int c = 0; c < 16; ++c) cnt += (eu[c] >= cand) ? 1 : 0;
        cnt = wsumi(cnt);
        if (cnt >= KK) thr = cand;
    }

    float mloc = -1e30f;
#pragma unroll
    for (int c = 0; c < 16; ++c) mloc = fmaxf(mloc, sc[c]);
    float mx = wmaxf(mloc);
    float ssum = 0.f;
#pragma unroll
    for (int c = 0; c < 16; ++c) ssum += (eu[c] >= thr) ? expf(sc[c] - mx) : 0.f;
    ssum = wsum(ssum);
    float inv = 1.f / ssum;

    float cx[32];
#pragma unroll
    for (int dh = 0; dh < 32; ++dh) cx[dh] = 0.f;
#pragma unroll 1
    for (int c = 0; c < 16; ++c) {
        float a = (eu[c] >= thr) ? expf(sc[c] - mx) * inv : 0.f;
        int n = c * 32 + lane;
#pragma unroll
        for (int dh = 0; dh < 32; ++dh)
            cx[dh] = fmaf(a, vt[n * 32 + ((dh + n) & 31)], cx[dh]);
    }

    float* cw = cp + warp * 1024;
#pragma unroll
    for (int dh = 0; dh < 32; ++dh) cw[lane * 32 + ((dh + lane) & 31)] = cx[dh];
    __syncwarp();
    float tot = 0.f;
#pragma unroll
    for (int src = 0; src < 32; ++src) tot += cw[src * 32 + ((lane + src) & 31)];
    int bb = bh >> 2, h = bh & 3;
    g_ctx[(bb * SL + qrow) * DD + h * 32 + lane] = tot;
}

// ---------------- K6: small 128x128 GEMMs ----------------
__global__ void gemm128_kernel(const float* __restrict__ W, const float* __restrict__ bias,
                               int mode) {
    __shared__ float xs[32 * 128];
    const float* in = mode ? g_out : g_ctx;
    float* out = mode ? g_d1 : g_out;
    int tid = threadIdx.x;
    int rowbase = blockIdx.x * 32;
    for (int idx = tid; idx < 4096; idx += 256) xs[idx] = in[rowbase * 128 + idx];
    __syncthreads();
    int rh = tid >> 7, jj = tid & 127;
    float acc[16];
#pragma unroll
    for (int r = 0; r < 16; ++r) acc[r] = 0.f;
    for (int k = 0; k < 128; ++k) {
        float wv = W[k * 128 + jj];
#pragma unroll
        for (int r = 0; r < 16; ++r) acc[r] = fmaf(xs[(rh * 16 + r) * 128 + k], wv, acc[r]);
    }
    float bb = mode ? bias[jj] : 0.f;
#pragma unroll
    for (int r = 0; r < 16; ++r) {
        float v = acc[r] + bb;
        if (mode) v = fmaxf(v, 0.f);
        out[(rowbase + rh * 16 + r) * 128 + jj] = v;
    }
}

// ---------------- K7: decoder [2048,128]@[128,32000] ----------------
__global__ void __launch_bounds__(256) decoder_kernel(const float* __restrict__ Wd2,
                                                      const float* __restrict__ bd2,
                                                      float* __restrict__ out) {
    extern __shared__ float At[];   // 128*132 transposed A tile
    int tid = threadIdx.x;
    int rowbase = blockIdx.x * 128;
    for (int idx = tid; idx < 16384; idx += 256) {
        int r = idx >> 7, k = idx & 127;
        At[k * 132 + r] = g_d1[(rowbase + r) * 128 + k];
    }
    __syncthreads();
    int j = blockIdx.y * 64 + (tid & 63);
    int rq = tid >> 6;
    float acc[32];
#pragma unroll
    for (int r = 0; r < 32; ++r) acc[r] = 0.f;
    const float* Bp = Wd2 + j;
    for (int k = 0; k < 128; ++k) {
        float w = Bp[(size_t)k * VOCAB];
        const float4* a4 = reinterpret_cast<const float4*>(At + k * 132) + rq * 8;
#pragma unroll
        for (int rr = 0; rr < 8; ++rr) {
            float4 a = a4[rr];
            acc[rr * 4 + 0] = fmaf(a.x, w, acc[rr * 4 + 0]);
            acc[rr * 4 + 1] = fmaf(a.y, w, acc[rr * 4 + 1]);
            acc[rr * 4 + 2] = fmaf(a.z, w, acc[rr * 4 + 2]);
            acc[rr * 4 + 3] = fmaf(a.w, w, acc[rr * 4 + 3]);
        }
    }
    float bb = bd2[j];
#pragma unroll
    for (int rr = 0; rr < 8; ++rr)
#pragma unroll
        for (int c = 0; c < 4; ++c) {
            int row = rowbase + rq * 32 + rr * 4 + c;
            out[(size_t)row * VOCAB + j] = acc[rr * 4 + c] + bb;
        }
}

// ---------------- launch ----------------
extern "C" void kernel_launch(void* const* d_in, const int* in_sizes, int n_in,
                              void* d_out, int out_size) {
    int off = (n_in > 30) ? 1 : 0;  // skip task_id if present
    const int*   seq  = (const int*)d_in[0];
    const float* emb  = (const float*)d_in[1 + off];
    const float* pos  = (const float*)d_in[2 + off];
    const float* Wr1  = (const float*)d_in[3 + off];
    const float* br1  = (const float*)d_in[4 + off];
    const float* Wr2  = (const float*)d_in[5 + off];
    const float* br2  = (const float*)d_in[6 + off];
    const float* ln_g = (const float*)d_in[7 + off];
    const float* ln_b = (const float*)d_in[8 + off];
    const float* eW1  = (const float*)d_in[9 + off];
    const float* eb1  = (const float*)d_in[10 + off];
    const float* e1g  = (const float*)d_in[11 + off];
    const float* e1b  = (const float*)d_in[12 + off];
    const float* eW2  = (const float*)d_in[13 + off];
    const float* eb2  = (const float*)d_in[14 + off];
    const float* e2g  = (const float*)d_in[15 + off];
    const float* e2b  = (const float*)d_in[16 + off];
    const float* eW3  = (const float*)d_in[17 + off];
    const float* eb3  = (const float*)d_in[18 + off];
    const float* mem0 = (const float*)d_in[19 + off];
    const float* Wmsg = (const float*)d_in[20 + off];
    const float* conn0= (const float*)d_in[21 + off];
    const float* Wq   = (const float*)d_in[22 + off];
    const float* Wk   = (const float*)d_in[23 + off];
    const float* Wv   = (const float*)d_in[24 + off];
    const float* Wo   = (const float*)d_in[25 + off];
    const float* Wd1  = (const float*)d_in[26 + off];
    const float* bd1  = (const float*)d_in[27 + off];
    const float* Wd2  = (const float*)d_in[28 + off];
    const float* bd2  = (const float*)d_in[29 + off];

    cudaFuncSetAttribute(conn_kernel, cudaFuncAttributeMaxDynamicSharedMemorySize, NB * SL * MM * 4);
    cudaFuncSetAttribute(scan_kernel, cudaFuncAttributeMaxDynamicSharedMemorySize, SCAN_SMEM_BYTES);
    cudaFuncSetAttribute(attn_kernel, cudaFuncAttributeMaxDynamicSharedMemorySize, 40960 * 4);
    cudaFuncSetAttribute(decoder_kernel, cudaFuncAttributeMaxDynamicSharedMemorySize, 128 * 132 * 4);

    embed_kernel<<<NB * SL, DD>>>(seq, emb, pos);
    gates_kernel<<<NB * SL / 8, 256>>>(Wr1, br1, Wr2, br2);
    conn_kernel<<<1, 64, NB * SL * MM * 4>>>(conn0);
    scan_kernel<<<NB * MM, 256, SCAN_SMEM_BYTES>>>(mem0, Wmsg, ln_g, ln_b,
                                                   eW1, eb1, e1g, e1b,
                                                   eW2, eb2, e2g, e2b, eW3, eb3);
    qkv_kernel<<<NB * SL / 32, 256>>>(Wq, Wk, Wv);
    attn_kernel<<<dim3(NB * 4, SL / 8), 256, 40960 * 4>>>();
    gemm128_kernel<<<NB * SL / 32, 256>>>(Wo, bd1, 0);   // ctx @ Wo -> g_out
    gemm128_kernel<<<NB * SL / 32, 256>>>(Wd1, bd1, 1);  // relu(g_out @ Wd1 + bd1) -> g_d1
    decoder_kernel<<<dim3(NB * SL / 128, VOCAB / 64), 256, 128 * 132 * 4>>>(Wd2, bd2, (float*)d_out);
}

// round 6
// speedup vs baseline: 2.0374x; 1.2637x over previous
#include <cuda_runtime.h>
#include <cooperative_groups.h>
#include <math.h>

namespace cg = cooperative_groups;

#define NB 4
#define SL 512
#define VOCAB 32000
#define DD 128
#define MM 8
#define NM 16
#define KK 153
#define LAMBDA 0.0025f
#define SCALE_D 0.08838834764831845f   /* 1/sqrt(128) */
#define SCALE_DH 0.17677669529663687f  /* 1/sqrt(32)  */

// ---------------- scratch ----------------
__device__ float g_x[NB*SL*DD];
__device__ float g_gates[NB*SL*MM];
__device__ float g_conn[SL*MM*MM];
__device__ float g_out[NB*SL*DD];
__device__ float g_q[NB*4*SL*32];
__device__ float g_k[NB*4*SL*32];
__device__ float g_v[NB*4*SL*32];
__device__ float g_ctx[NB*SL*DD];
__device__ float g_d1[NB*SL*DD];

// ---------------- helpers ----------------
__device__ __forceinline__ float wsum(float v) {
#pragma unroll
    for (int o = 16; o; o >>= 1) v += __shfl_xor_sync(0xffffffffu, v, o);
    return v;
}
__device__ __forceinline__ float wmaxf(float v) {
#pragma unroll
    for (int o = 16; o; o >>= 1) v = fmaxf(v, __shfl_xor_sync(0xffffffffu, v, o));
    return v;
}
__device__ __forceinline__ int wsumi(int v) {
#pragma unroll
    for (int o = 16; o; o >>= 1) v += __shfl_xor_sync(0xffffffffu, v, o);
    return v;
}

// ---------------- K0: embedding + pos ----------------
__global__ void embed_kernel(const int* __restrict__ seq,
                             const float* __restrict__ emb,
                             const float* __restrict__ pos) {
    int row = blockIdx.x;            // b*SL + s
    int d = threadIdx.x;
    int s = row & (SL - 1);
    int tok = seq[row];
    g_x[row * DD + d] = emb[tok * DD + d] + pos[s * DD + d];
}

// ---------------- K1: router gates ----------------
__global__ void gates_kernel(const float* __restrict__ Wr1, const float* __restrict__ br1,
                             const float* __restrict__ Wr2, const float* __restrict__ br2) {
    __shared__ float xs[8][DD];
    int warp = threadIdx.x >> 5, lane = threadIdx.x & 31;
    int row = blockIdx.x * 8 + warp;
    const float* xr = g_x + row * DD;
#pragma unroll
    for (int c = 0; c < 4; ++c) xs[warp][lane + 32 * c] = xr[lane + 32 * c];
    __syncwarp();

    float acc[4] = {0.f, 0.f, 0.f, 0.f};
    for (int k = 0; k < DD; ++k) {
        float a = xs[warp][k];
#pragma unroll
        for (int c = 0; c < 4; ++c) acc[c] = fmaf(a, Wr1[k * DD + lane + 32 * c], acc[c]);
    }
    float t1[4];
#pragma unroll
    for (int c = 0; c < 4; ++c) t1[c] = fmaxf(acc[c] + br1[lane + 32 * c], 0.f);

    float y[MM];
#pragma unroll
    for (int m = 0; m < MM; ++m) {
        float p = 0.f;
#pragma unroll
        for (int c = 0; c < 4; ++c) p = fmaf(t1[c], Wr2[(lane + 32 * c) * MM + m], p);
        p = wsum(p);
        y[m] = p + br2[m];
    }
    float mx = y[0];
#pragma unroll
    for (int m = 1; m < MM; ++m) mx = fmaxf(mx, y[m]);
    float ssum = 0.f;
#pragma unroll
    for (int m = 0; m < MM; ++m) { y[m] = expf(y[m] - mx); ssum += y[m]; }
    if (lane == 0) {
        float inv = 1.f / ssum;
#pragma unroll
        for (int m = 0; m < MM; ++m) g_gates[row * MM + m] = y[m] * inv;
    }
}

// ---------------- K2: Hebbian conn prefix ----------------
__global__ void conn_kernel(const float* __restrict__ conn0) {
    extern __shared__ float gs[];   // NB*SL*MM floats
    int tid = threadIdx.x;          // 64 threads
    for (int i = tid; i < NB * SL * MM; i += 64) gs[i] = g_gates[i];
    __syncthreads();
    int i = tid >> 3, j = tid & 7;
    float c = conn0[tid];
    for (int t = 0; t < SL; ++t) {
        g_conn[t * 64 + tid] = c;
        float v = 0.f;
#pragma unroll
        for (int b = 0; b < NB; ++b)
            v += gs[(b * SL + t) * MM + i] * gs[(b * SL + t) * MM + j];
        c += LAMBDA * v;
    }
}

// ---------------- K3: scan — 8-CTA cluster per batch, 512 threads ----------------
// SMEM float offsets
#define XW1   0        // 16384 (own module eW1)
#define XW2   16384
#define XW3   32768
#define XMEM  49152    // 2048
#define XB1   51200
#define XE1G  51328
#define XE1B  51456
#define XB2   51584
#define XE2G  51712
#define XE2B  51840
#define XB3   51968
#define XLNG  52096
#define XLNB  52224
#define XCUR  52352
#define XCOMB 52480
#define XH1   52608
#define XH2   52736
#define XMSG  52864
#define XAGG  52992
#define XSOWN 53120
#define XEX0  53248
#define XEX1  53376
#define XEX2  53504
#define XST   53632    // 1024 all-module states
#define XSA   54656    // 1024 all-module s
#define XPART 55680    // 2048 (16 k-groups x 128)
#define XATT  57728    // 16
#define XG    57744    // 8
#define XCR   57752    // 8
#define XCG   57760    // 8
#define XRS   57768    // 16
#define XRQ   57784    // 16
#define XTOT  57800
#define SCAN_SMEM_BYTES (XTOT * 4)

// 16-slot memory attention (16 warps, 1 slot each)
__device__ __forceinline__ void mem_attn16(float* sm, int tid, int vecoff) {
    int warp = tid >> 5, lane = tid & 31;
    float p = 0.f;
#pragma unroll
    for (int c = 0; c < 4; ++c) {
        int k = lane + 32 * c;
        p = fmaf(sm[vecoff + k], sm[XMEM + warp * DD + k], p);
    }
    p = wsum(p);
    if (lane == 0) sm[XATT + warp] = p * SCALE_D;
    __syncthreads();
    if (warp == 0) {
        float vv = (lane < NM) ? sm[XATT + lane] : -1e30f;
        float mx = wmaxf(vv);
        float e = (lane < NM) ? expf(vv - mx) : 0.f;
        float ss = wsum(e);
        if (lane < NM) sm[XATT + lane] = e / ss;
    }
    __syncthreads();
}

// 128x128 matvec, W in SMEM, float4 over j, 16 k-groups of 8
__device__ __forceinline__ void mv4s(const float* __restrict__ Wsm,
                                     const float* __restrict__ xp,
                                     float* sm, int tid) {
    int kq = tid >> 5, jq = tid & 31;
    const float4* W4 = reinterpret_cast<const float4*>(Wsm) + (kq * 8) * 32 + jq;
    float4 xa = *reinterpret_cast<const float4*>(xp + kq * 8);
    float4 xb = *reinterpret_cast<const float4*>(xp + kq * 8 + 4);
    float xs[8] = {xa.x, xa.y, xa.z, xa.w, xb.x, xb.y, xb.z, xb.w};
    float4 acc = make_float4(0.f, 0.f, 0.f, 0.f);
#pragma unroll
    for (int k = 0; k < 8; ++k) {
        float4 w = W4[k * 32];
        acc.x = fmaf(xs[k], w.x, acc.x);
        acc.y = fmaf(xs[k], w.y, acc.y);
        acc.z = fmaf(xs[k], w.z, acc.z);
        acc.w = fmaf(xs[k], w.w, acc.w);
    }
    reinterpret_cast<float4*>(sm + XPART)[kq * 32 + jq] = acc;
}

// same but W in global (Wmsg)
__device__ __forceinline__ void mv4g(const float* __restrict__ Wg,
                                     const float* __restrict__ xp,
                                     float* sm, int tid) {
    int kq = tid >> 5, jq = tid & 31;
    const float4* W4 = reinterpret_cast<const float4*>(Wg) + (kq * 8) * 32 + jq;
    float4 xa = *reinterpret_cast<const float4*>(xp + kq * 8);
    float4 xb = *reinterpret_cast<const float4*>(xp + kq * 8 + 4);
    float xs[8] = {xa.x, xa.y, xa.z, xa.w, xb.x, xb.y, xb.z, xb.w};
    float4 acc = make_float4(0.f, 0.f, 0.f, 0.f);
#pragma unroll
    for (int k = 0; k < 8; ++k) {
        float4 w = __ldg(&W4[k * 32]);
        acc.x = fmaf(xs[k], w.x, acc.x);
        acc.y = fmaf(xs[k], w.y, acc.y);
        acc.z = fmaf(xs[k], w.z, acc.z);
        acc.w = fmaf(xs[k], w.w, acc.w);
    }
    reinterpret_cast<float4*>(sm + XPART)[kq * 32 + jq] = acc;
}

__device__ __forceinline__ float red16(const float* sm, int tid) {  // tid < 128
    float v = 0.f;
#pragma unroll
    for (int q = 0; q < 16; ++q) v += sm[XPART + q * 128 + tid];
    return v;
}

// LN over 128 of v (valid tid<128), optional relu, write dst
__device__ __forceinline__ void ln_write(float* sm, int tid, float v,
                                         int goff, int boff, int dstoff, bool do_relu) {
    int warp = tid >> 5, lane = tid & 31;
    if (tid < 128) {
        float s1 = wsum(v), s2 = wsum(v * v);
        if (lane == 0) { sm[XRS + warp] = s1; sm[XRQ + warp] = s2; }
    }
    __syncthreads();
    if (tid < 128) {
        float t1 = sm[XRS + 0] + sm[XRS + 1] + sm[XRS + 2] + sm[XRS + 3];
        float t2 = sm[XRQ + 0] + sm[XRQ + 1] + sm[XRQ + 2] + sm[XRQ + 3];
        float mean = t1 * (1.f / 128.f);
        float var = t2 * (1.f / 128.f) - mean * mean;
        float inv = rsqrtf(var + 1e-5f);
        float r = (v - mean) * inv * sm[goff + tid] + sm[boff + tid];
        sm[dstoff + tid] = do_relu ? fmaxf(r, 0.f) : r;
    }
    __syncthreads();
}

// DSMEM exchange: all CTAs wrote sm[exoff..exoff+128); gather all 8 ranks into dstoff
__device__ __forceinline__ void exch(cg::cluster_group& cl, float* sm, int exoff, int dstoff, int tid) {
    cl.sync();
    if (tid < 256) {
        int r = tid >> 5, l = tid & 31;
        const float4* rs = (const float4*)cl.map_shared_rank(sm + exoff, r);
        reinterpret_cast<float4*>(sm + dstoff)[r * 32 + l] = rs[l];
    }
    __syncthreads();
}

__global__ void __launch_bounds__(512, 1) __cluster_dims__(MM, 1, 1) scan_kernel(
    const float* __restrict__ mem0, const float* __restrict__ Wmsg,
    const float* __restrict__ ln_g, const float* __restrict__ ln_b,
    const float* __restrict__ eW1, const float* __restrict__ eb1,
    const float* __restrict__ e1g, const float* __restrict__ e1b,
    const float* __restrict__ eW2, const float* __restrict__ eb2,
    const float* __restrict__ e2g, const float* __restrict__ e2b,
    const float* __restrict__ eW3, const float* __restrict__ eb3) {
    extern __shared__ float sm[];
    cg::cluster_group cluster = cg::this_cluster();
    int tid = threadIdx.x;
    int rank = (int)cluster.block_rank();        // module index
    int b = blockIdx.x >> 3;                     // batch index

    // one-time loads
    {
        const float* w1 = eW1 + (size_t)rank * 16384;
        const float* w2 = eW2 + (size_t)rank * 16384;
        const float* w3 = eW3 + (size_t)rank * 16384;
        for (int i = tid; i < 16384; i += 512) {
            sm[XW1 + i] = w1[i];
            sm[XW2 + i] = w2[i];
            sm[XW3 + i] = w3[i];
        }
        for (int i = tid; i < 2048; i += 512) sm[XMEM + i] = mem0[i];
        if (tid < 128) {
            sm[XB1 + tid]  = eb1[rank * 128 + tid];
            sm[XE1G + tid] = e1g[rank * 128 + tid];
            sm[XE1B + tid] = e1b[rank * 128 + tid];
            sm[XB2 + tid]  = eb2[rank * 128 + tid];
            sm[XE2G + tid] = e2g[rank * 128 + tid];
            sm[XE2B + tid] = e2b[rank * 128 + tid];
            sm[XB3 + tid]  = eb3[rank * 128 + tid];
            sm[XLNG + tid] = ln_g[tid];
            sm[XLNB + tid] = ln_b[tid];
        }
    }
    __syncthreads();

    for (int t = 0; t < SL; ++t) {
        // step loader
        if (tid < 128) sm[XCUR + tid] = g_x[(b * SL + t) * DD + tid];
        else if (tid < 136) sm[XG + tid - 128] = g_gates[(b * SL + t) * MM + (tid - 128)];
        else if (tid < 144) sm[XCR + tid - 136] = g_conn[t * 64 + rank * 8 + (tid - 136)];
        __syncthreads();
        if (tid < 8) sm[XCG + tid] = sm[XCR + tid] * sm[XG + tid];

        // read-attention over memory (replicated)
        mem_attn16(sm, tid, XCUR);

        // retrieved + combined, LN
        float combv = 0.f;
        if (tid < 128) {
            float rr = 0.f;
#pragma unroll
            for (int n = 0; n < NM; ++n) rr = fmaf(sm[XATT + n], sm[XMEM + n * DD + tid], rr);
            combv = sm[XCUR + tid] + rr;
        }
        ln_write(sm, tid, combv, XLNG, XLNB, XCOMB, false);

        // expert layer 1
        mv4s(sm + XW1, sm + XCOMB, sm, tid);
        __syncthreads();
        {
            float v = (tid < 128) ? (red16(sm, tid) + sm[XB1 + tid]) : 0.f;
            ln_write(sm, tid, v, XE1G, XE1B, XH1, true);
        }
        // expert layer 2
        mv4s(sm + XW2, sm + XH1, sm, tid);
        __syncthreads();
        {
            float v = (tid < 128) ? (red16(sm, tid) + sm[XB2 + tid]) : 0.f;
            ln_write(sm, tid, v, XE2G, XE2B, XH2, true);
        }
        // expert layer 3 -> own state
        mv4s(sm + XW3, sm + XH2, sm, tid);
        __syncthreads();
        if (tid < 128) {
            float v = red16(sm, tid) + sm[XB3 + tid];
            sm[XSOWN + tid] = v;
            sm[XEX0 + tid] = v;
        }
        // exchange states -> XST (cl.sync provides both cta- and cluster-wide order)
        exch(cluster, sm, XEX0, XST, tid);

        // MP step 1
        if (tid < 128) {
            float mv = 0.f;
#pragma unroll
            for (int jm = 0; jm < MM; ++jm)
                mv = fmaf(sm[XCG + jm], sm[XST + jm * 128 + tid], mv);
            sm[XMSG + tid] = mv;
        }
        __syncthreads();
        mv4g(Wmsg, sm + XMSG, sm, tid);
        __syncthreads();
        if (tid < 128) {
            float y = red16(sm, tid);
            float ns = sm[XSOWN + tid] + fmaxf(y, 0.f);
            sm[XSOWN + tid] = ns;
            sm[XEX1 + tid] = ns;
        }
        exch(cluster, sm, XEX1, XSA, tid);

        // MP step 2
        if (tid < 128) {
            float mv = 0.f;
#pragma unroll
            for (int jm = 0; jm < MM; ++jm)
                mv = fmaf(sm[XCG + jm], sm[XSA + jm * 128 + tid], mv);
            sm[XMSG + tid] = mv;
        }
        __syncthreads();
        mv4g(Wmsg, sm + XMSG, sm, tid);
        __syncthreads();
        if (tid < 128) {
            float y = red16(sm, tid);
            sm[XEX2 + tid] = sm[XSOWN + tid] + fmaxf(y, 0.f);
        }
        exch(cluster, sm, XEX2, XSA, tid);

        // agg = sum_m g_m * states_m + mean_m s_m (replicated)
        if (tid < 128) {
            float a = 0.f, ms = 0.f;
#pragma unroll
            for (int m = 0; m < MM; ++m) {
                a = fmaf(sm[XG + m], sm[XST + m * 128 + tid], a);
                ms += sm[XSA + m * 128 + tid];
            }
            sm[XAGG + tid] = a + 0.125f * ms;
        }
        __syncthreads();

        // write-attention + memory update (replicated, deterministic)
        mem_attn16(sm, tid, XAGG);
#pragma unroll
        for (int e = tid; e < 2048; e += 512) {
            int n = e >> 7, d = e & 127;
            sm[XMEM + e] += sm[XATT + n] * sm[XAGG + d];
        }
        if (rank == 0 && tid < 128) g_out[(b * SL + t) * DD + tid] = sm[XAGG + tid];
        __syncthreads();
    }
}

// ---------------- K4: QKV projections ----------------
__global__ void qkv_kernel(const float* __restrict__ Wq, const float* __restrict__ Wk,
                           const float* __restrict__ Wv) {
    __shared__ float xs[32 * 128];
    int tid = threadIdx.x;
    int rowbase = blockIdx.x * 32;
    for (int idx = tid; idx < 4096; idx += 256) xs[idx] = g_out[rowbase * 128 + idx];
    __syncthreads();
    int rh = tid >> 7, jj = tid & 127;
    const float* Ws[3] = {Wq, Wk, Wv};
    float* Os[3] = {g_q, g_k, g_v};
#pragma unroll 1
    for (int w = 0; w < 3; ++w) {
        float acc[16];
#pragma unroll
        for (int r = 0; r < 16; ++r) acc[r] = 0.f;
        const float* W = Ws[w];
        for (int k = 0; k < 128; ++k) {
            float wv = W[k * 128 + jj];
#pragma unroll
            for (int r = 0; r < 16; ++r) acc[r] = fmaf(xs[(rh * 16 + r) * 128 + k], wv, acc[r]);
        }
        int h = jj >> 5, dh = jj & 31;
#pragma unroll
        for (int r = 0; r < 16; ++r) {
            int row = rowbase + rh * 16 + r;
            int bb = row >> 9, s = row & 511;
            Os[w][((bb * 4 + h) * SL + s) * 32 + dh] = acc[r];
        }
    }
}

// ---------------- K5: sparse attention ----------------
__global__ void __launch_bounds__(256) attn_kernel() {
    extern __shared__ float ash[];
    float* kt = ash;              // 16384
    float* vt = ash + 16384;      // 16384
    float* cp = ash + 32768;      // 8192
    int tid = threadIdx.x, warp = tid >> 5, lane = tid & 31;
    int bh = blockIdx.x;
    const float* kb = g_k + bh * SL * 32;
    const float* vb = g_v + bh * SL * 32;
    for (int idx = tid; idx < SL * 32; idx += 256) {
        int n = idx >> 5, dh = idx & 31, sw = (dh + n) & 31;
        kt[n * 32 + sw] = kb[idx];
        vt[n * 32 + sw] = vb[idx];
    }
    __syncthreads();

    int qrow = blockIdx.y * 8 + warp;
    float qv = g_q[bh * SL * 32 + qrow * 32 + lane];
    float sc[16];
#pragma unroll
    for (int c = 0; c < 16; ++c) sc[c] = 0.f;
    for (int dh = 0; dh < 32; ++dh) {
        float qd = __shfl_sync(0xffffffffu, qv, dh);
#pragma unroll
        for (int c = 0; c < 16; ++c) {
            int n = c * 32 + lane;
            sc[c] = fmaf(qd, kt[n * 32 + ((dh + n) & 31)], sc[c]);
        }
    }
#pragma unroll
    for (int c = 0; c < 16; ++c) sc[c] *= SCALE_DH;

    unsigned eu[16];
#pragma unroll
    for (int c = 0; c < 16; ++c) {
        unsigned u = __float_as_uint(sc[c]);
        eu[c] = (u & 0x80000000u) ? ~u : (u | 0x80000000u);
    }
    unsigned thr = 0;
    for (int bit = 31; bit >= 0; --bit) {
        unsigned cand = thr | (1u << bit);
        int cnt = 0;
#pragma unroll
        for (int c = 0; c < 16; ++c) cnt += (eu[c] >= cand) ? 1 : 0;
        cnt = wsumi(cnt);
        if (cnt >= KK) thr = cand;
    }

    float mloc = -1e30f;
#pragma unroll
    for (int c = 0; c < 16; ++c) mloc = fmaxf(mloc, sc[c]);
    float mx = wmaxf(mloc);
    float ssum = 0.f;
#pragma unroll
    for (int c = 0; c < 16; ++c) ssum += (eu[c] >= thr) ? expf(sc[c] - mx) : 0.f;
    ssum = wsum(ssum);
    float inv = 1.f / ssum;

    float cx[32];
#pragma unroll
    for (int dh = 0; dh < 32; ++dh) cx[dh] = 0.f;
#pragma unroll 1
    for (int c = 0; c < 16; ++c) {
        float a = (eu[c] >= thr) ? expf(sc[c] - mx) * inv : 0.f;
        int n = c * 32 + lane;
#pragma unroll
        for (int dh = 0; dh < 32; ++dh)
            cx[dh] = fmaf(a, vt[n * 32 + ((dh + n) & 31)], cx[dh]);
    }

    float* cw = cp + warp * 1024;
#pragma unroll
    for (int dh = 0; dh < 32; ++dh) cw[lane * 32 + ((dh + lane) & 31)] = cx[dh];
    __syncwarp();
    float tot = 0.f;
#pragma unroll
    for (int src = 0; src < 32; ++src) tot += cw[src * 32 + ((lane + src) & 31)];
    int bb = bh >> 2, h = bh & 3;
    g_ctx[(bb * SL + qrow) * DD + h * 32 + lane] = tot;
}

// ---------------- K6: small 128x128 GEMMs ----------------
__global__ void gemm128_kernel(const float* __restrict__ W, const float* __restrict__ bias,
                               int mode) {
    __shared__ float xs[32 * 128];
    const float* in = mode ? g_out : g_ctx;
    float* out = mode ? g_d1 : g_out;
    int tid = threadIdx.x;
    int rowbase = blockIdx.x * 32;
    for (int idx = tid; idx < 4096; idx += 256) xs[idx] = in[rowbase * 128 + idx];
    __syncthreads();
    int rh = tid >> 7, jj = tid & 127;
    float acc[16];
#pragma unroll
    for (int r = 0; r < 16; ++r) acc[r] = 0.f;
    for (int k = 0; k < 128; ++k) {
        float wv = W[k * 128 + jj];
#pragma unroll
        for (int r = 0; r < 16; ++r) acc[r] = fmaf(xs[(rh * 16 + r) * 128 + k], wv, acc[r]);
    }
    float bb = mode ? bias[jj] : 0.f;
#pragma unroll
    for (int r = 0; r < 16; ++r) {
        float v = acc[r] + bb;
        if (mode) v = fmaxf(v, 0.f);
        out[(rowbase + rh * 16 + r) * 128 + jj] = v;
    }
}

// ---------------- K7: decoder [2048,128]@[128,32000] ----------------
__global__ void __launch_bounds__(256) decoder_kernel(const float* __restrict__ Wd2,
                                                      const float* __restrict__ bd2,
                                                      float* __restrict__ out) {
    extern __shared__ float At[];   // 128*132 transposed A tile
    int tid = threadIdx.x;
    int rowbase = blockIdx.x * 128;
    for (int idx = tid; idx < 16384; idx += 256) {
        int r = idx >> 7, k = idx & 127;
        At[k * 132 + r] = g_d1[(rowbase + r) * 128 + k];
    }
    __syncthreads();
    int j = blockIdx.y * 64 + (tid & 63);
    int rq = tid >> 6;
    float acc[32];
#pragma unroll
    for (int r = 0; r < 32; ++r) acc[r] = 0.f;
    const float* Bp = Wd2 + j;
    for (int k = 0; k < 128; ++k) {
        float w = Bp[(size_t)k * VOCAB];
        const float4* a4 = reinterpret_cast<const float4*>(At + k * 132) + rq * 8;
#pragma unroll
        for (int rr = 0; rr < 8; ++rr) {
            float4 a = a4[rr];
            acc[rr * 4 + 0] = fmaf(a.x, w, acc[rr * 4 + 0]);
            acc[rr * 4 + 1] = fmaf(a.y, w, acc[rr * 4 + 1]);
            acc[rr * 4 + 2] = fmaf(a.z, w, acc[rr * 4 + 2]);
            acc[rr * 4 + 3] = fmaf(a.w, w, acc[rr * 4 + 3]);
        }
    }
    float bb = bd2[j];
#pragma unroll
    for (int rr = 0; rr < 8; ++rr)
#pragma unroll
        for (int c = 0; c < 4; ++c) {
            int row = rowbase + rq * 32 + rr * 4 + c;
            out[(size_t)row * VOCAB + j] = acc[rr * 4 + c] + bb;
        }
}

// ---------------- launch ----------------
extern "C" void kernel_launch(void* const* d_in, const int* in_sizes, int n_in,
                              void* d_out, int out_size) {
    int off = (n_in > 30) ? 1 : 0;  // skip task_id if present
    const int*   seq  = (const int*)d_in[0];
    const float* emb  = (const float*)d_in[1 + off];
    const float* pos  = (const float*)d_in[2 + off];
    const float* Wr1  = (const float*)d_in[3 + off];
    const float* br1  = (const float*)d_in[4 + off];
    const float* Wr2  = (const float*)d_in[5 + off];
    const float* br2  = (const float*)d_in[6 + off];
    const float* ln_g = (const float*)d_in[7 + off];
    const float* ln_b = (const float*)d_in[8 + off];
    const float* eW1  = (const float*)d_in[9 + off];
    const float* eb1  = (const float*)d_in[10 + off];
    const float* e1g  = (const float*)d_in[11 + off];
    const float* e1b  = (const float*)d_in[12 + off];
    const float* eW2  = (const float*)d_in[13 + off];
    const float* eb2  = (const float*)d_in[14 + off];
    const float* e2g  = (const float*)d_in[15 + off];
    const float* e2b  = (const float*)d_in[16 + off];
    const float* eW3  = (const float*)d_in[17 + off];
    const float* eb3  = (const float*)d_in[18 + off];
    const float* mem0 = (const float*)d_in[19 + off];
    const float* Wmsg = (const float*)d_in[20 + off];
    const float* conn0= (const float*)d_in[21 + off];
    const float* Wq   = (const float*)d_in[22 + off];
    const float* Wk   = (const float*)d_in[23 + off];
    const float* Wv   = (const float*)d_in[24 + off];
    const float* Wo   = (const float*)d_in[25 + off];
    const float* Wd1  = (const float*)d_in[26 + off];
    const float* bd1  = (const float*)d_in[27 + off];
    const float* Wd2  = (const float*)d_in[28 + off];
    const float* bd2  = (const float*)d_in[29 + off];

    cudaFuncSetAttribute(conn_kernel, cudaFuncAttributeMaxDynamicSharedMemorySize, NB * SL * MM * 4);
    cudaFuncSetAttribute(scan_kernel, cudaFuncAttributeMaxDynamicSharedMemorySize, SCAN_SMEM_BYTES);
    cudaFuncSetAttribute(attn_kernel, cudaFuncAttributeMaxDynamicSharedMemorySize, 40960 * 4);
    cudaFuncSetAttribute(decoder_kernel, cudaFuncAttributeMaxDynamicSharedMemorySize, 128 * 132 * 4);

    embed_kernel<<<NB * SL, DD>>>(seq, emb, pos);
    gates_kernel<<<NB * SL / 8, 256>>>(Wr1, br1, Wr2, br2);
    conn_kernel<<<1, 64, NB * SL * MM * 4>>>(conn0);
    scan_kernel<<<NB * MM, 512, SCAN_SMEM_BYTES>>>(mem0, Wmsg, ln_g, ln_b,
                                                   eW1, eb1, e1g, e1b,
                                                   eW2, eb2, e2g, e2b, eW3, eb3);
    qkv_kernel<<<NB * SL / 32, 256>>>(Wq, Wk, Wv);
    attn_kernel<<<dim3(NB * 4, SL / 8), 256, 40960 * 4>>>();
    gemm128_kernel<<<NB * SL / 32, 256>>>(Wo, bd1, 0);   // ctx @ Wo -> g_out
    gemm128_kernel<<<NB * SL / 32, 256>>>(Wd1, bd1, 1);  // relu(g_out @ Wd1 + bd1) -> g_d1
    decoder_kernel<<<dim3(NB * SL / 128, VOCAB / 64), 256, 128 * 132 * 4>>>(Wd2, bd2, (float*)d_out);
}